// round 2
// baseline (speedup 1.0000x reference)
#include <cuda_runtime.h>
#include <cstdint>

// Problem constants
#define BB 64
#define TT 2048
#define HH 256
#define G4 1024
#define MTOT (BB * TT)

typedef unsigned long long ull;

// ---------- f32x2 helpers (FFMA2 is PTX-only; ptxas won't auto-fuse) ----------
__device__ __forceinline__ ull fma2(ull a, ull b, ull c) {
    ull d; asm("fma.rn.f32x2 %0,%1,%2,%3;" : "=l"(d) : "l"(a), "l"(b), "l"(c)); return d;
}
__device__ __forceinline__ ull pack2(float x, float y) {
    ull d; asm("mov.b64 %0,{%1,%2};" : "=l"(d) : "f"(x), "f"(y)); return d;
}
__device__ __forceinline__ float2 unpk2(ull a) {
    float2 r; asm("mov.b64 {%0,%1},%2;" : "=f"(r.x), "=f"(r.y) : "l"(a)); return r;
}

__device__ __forceinline__ uint32_t s2u(const void* p) {
    return (uint32_t)__cvta_generic_to_shared(p);
}
__device__ __forceinline__ void sts_cluster_b32(uint32_t saddr, uint32_t rank, uint32_t v) {
    asm volatile(
        "{.reg .b32 ra; mapa.shared::cluster.u32 ra, %0, %1; st.shared::cluster.b32 [ra], %2;}"
        :: "r"(saddr), "r"(rank), "r"(v) : "memory");
}
__device__ __forceinline__ void cluster_sync_() {
    asm volatile("barrier.cluster.arrive.aligned;\n\tbarrier.cluster.wait.aligned;" ::: "memory");
}
__device__ __forceinline__ uint32_t ctarank() {
    uint32_t r; asm("mov.u32 %0, %%cluster_ctarank;" : "=r"(r)); return r;
}

__device__ __forceinline__ float fsig(float x)  { return 1.0f / (1.0f + __expf(-x)); }
__device__ __forceinline__ float ftanh(float x) { return 2.0f / (1.0f + __expf(-2.0f * x)) - 1.0f; }

// ---------- scratch (device globals: allocation-free) ----------
__device__ float g_xg[(size_t)MTOT * G4];   // [B][T][1024] gate preactivations (bias folded)
__device__ float g_y0[(size_t)MTOT * HH];   // layer-1 output [B][T][256]
__device__ float g_y1[(size_t)MTOT * HH];   // layer-2 output [B][T][256]

// ============================================================================
// Phase A: xg[b*T+t][n] = sum_k A[m][k] * W[n][k] + b1[n] + b2[n]
// A: [M][256] row-major, W: [1024][256] row-major. f32x2 SGEMM, 128x64 tile.
// ============================================================================
__global__ void __launch_bounds__(256) gemm_kernel(
    const float* __restrict__ Ain, int useAin,
    const float* __restrict__ W,
    const float* __restrict__ b1, const float* __restrict__ b2)
{
    const float* A = useAin ? Ain : g_y0;
    float* C = g_xg;

    __shared__ float As[16][132];  // [k][m], padded
    __shared__ float Bs[16][68];   // [k][n], padded

    const int tid = threadIdx.x;
    const int bm = blockIdx.y * 128;
    const int bn = blockIdx.x * 64;
    const int tx = tid & 15;   // n / 4
    const int ty = tid >> 4;   // m / 8

    ull acc[8][2];
#pragma unroll
    for (int i = 0; i < 8; i++) { acc[i][0] = 0ull; acc[i][1] = 0ull; }

    for (int kt = 0; kt < HH; kt += 16) {
        // load A tile: 128 rows x 16 k (2 float4 / thread), store transposed
#pragma unroll
        for (int i = 0; i < 2; i++) {
            int idx = tid + i * 256;
            int r = idx >> 2, q = idx & 3;
            float4 v = *(const float4*)(A + (size_t)(bm + r) * HH + kt + q * 4);
            As[q * 4 + 0][r] = v.x; As[q * 4 + 1][r] = v.y;
            As[q * 4 + 2][r] = v.z; As[q * 4 + 3][r] = v.w;
        }
        {
            int r = tid >> 2, q = tid & 3;
            float4 v = *(const float4*)(W + (size_t)(bn + r) * HH + kt + q * 4);
            Bs[q * 4 + 0][r] = v.x; Bs[q * 4 + 1][r] = v.y;
            Bs[q * 4 + 2][r] = v.z; Bs[q * 4 + 3][r] = v.w;
        }
        __syncthreads();
#pragma unroll
        for (int k = 0; k < 16; k++) {
            float4 b4 = *(const float4*)&Bs[k][tx * 4];
            ull b01 = pack2(b4.x, b4.y);
            ull b23 = pack2(b4.z, b4.w);
            float4 a0 = *(const float4*)&As[k][ty * 8];
            float4 a1 = *(const float4*)&As[k][ty * 8 + 4];
            float am[8] = {a0.x, a0.y, a0.z, a0.w, a1.x, a1.y, a1.z, a1.w};
#pragma unroll
            for (int mi = 0; mi < 8; mi++) {
                ull ad = pack2(am[mi], am[mi]);
                acc[mi][0] = fma2(ad, b01, acc[mi][0]);
                acc[mi][1] = fma2(ad, b23, acc[mi][1]);
            }
        }
        __syncthreads();
    }

    float4 bias;
    bias.x = b1[bn + tx * 4 + 0] + b2[bn + tx * 4 + 0];
    bias.y = b1[bn + tx * 4 + 1] + b2[bn + tx * 4 + 1];
    bias.z = b1[bn + tx * 4 + 2] + b2[bn + tx * 4 + 2];
    bias.w = b1[bn + tx * 4 + 3] + b2[bn + tx * 4 + 3];
#pragma unroll
    for (int mi = 0; mi < 8; mi++) {
        float2 u = unpk2(acc[mi][0]);
        float2 v = unpk2(acc[mi][1]);
        float4 o = {u.x + bias.x, u.y + bias.y, v.x + bias.z, v.y + bias.w};
        *(float4*)(C + (size_t)(bm + ty * 8 + mi) * G4 + bn + tx * 4) = o;
    }
}

// ============================================================================
// Phase B: recurrent scan. 16 clusters x 8 CTAs; cluster handles 4 batches;
// CTA (rank s) owns h-dims [32s, 32s+32) and their 4 gate rows (128 rows),
// w_hh slice SMEM-resident (128 KB), h broadcast via DSMEM each step.
// ============================================================================
struct RS {
    float w[256][128];      // [k][local row], k-major (conflict-free lane reads)
    float h[2][256][4];     // double-buffered h: [buf][k-dim][batch]
    float red[128][4];      // k-split partial reduction
    float gates[4][32][4];  // activated gates [gate][dim][batch]
};

extern __shared__ __align__(16) char smem_raw[];

__global__ void __launch_bounds__(256, 1) __cluster_dims__(8, 1, 1)
rnn_kernel(const float* __restrict__ whh, int layer)
{
    RS* sm = (RS*)smem_raw;
    float* yout = layer ? g_y1 : g_y0;

    const int tid  = threadIdx.x;
    const int lane = tid & 31;
    const int wid  = tid >> 5;
    const int rg   = wid & 3;     // gate group (0:i 1:f 2:g 3:o)
    const int kh   = wid >> 2;    // k half
    const int s    = (int)ctarank();       // dim slice 0..7
    const int cl   = blockIdx.x >> 3;      // cluster id 0..15
    const int b0   = cl * 4;

    // Load w_hh slice transposed into SMEM: sm->w[k][lr] = whh[rglob(lr)][k]
    for (int idx = tid; idx < 128 * 256; idx += 256) {
        int lr = idx & 127;
        int k  = idx >> 7;
        int rglob = ((lr >> 5) << 8) + s * 32 + (lr & 31);
        sm->w[k][lr] = whh[(size_t)rglob * HH + k];
    }
    // zero h buffers
    for (int idx = tid; idx < 2 * 256 * 4; idx += 256) ((float*)sm->h)[idx] = 0.0f;
    float creg = 0.0f;  // cell state, live in threads 0..127
    __syncthreads();
    cluster_sync_();

    const int my_lr    = rg * 32 + lane;
    const int my_rglob = rg * 256 + s * 32 + lane;

    const float* xgp0 = g_xg + (size_t)(b0 + 0) * TT * G4 + my_rglob;
    const float* xgp1 = g_xg + (size_t)(b0 + 1) * TT * G4 + my_rglob;
    const float* xgp2 = g_xg + (size_t)(b0 + 2) * TT * G4 + my_rglob;
    const float* xgp3 = g_xg + (size_t)(b0 + 3) * TT * G4 + my_rglob;

    for (int t = 0; t < TT; t++) {
        const int p = t & 1;
        float xv0 = 0.f, xv1 = 0.f, xv2 = 0.f, xv3 = 0.f;
        if (kh == 0) {  // prefetch xg early; consumed after the k-loop
            const size_t off = (size_t)t * G4;
            xv0 = __ldg(xgp0 + off); xv1 = __ldg(xgp1 + off);
            xv2 = __ldg(xgp2 + off); xv3 = __ldg(xgp3 + off);
        }

        ull a01 = 0ull, a23 = 0ull;
        const float* wc = &sm->w[kh * 128][my_lr];
        const ull* hr = (const ull*)&sm->h[p][kh * 128][0];
#pragma unroll 8
        for (int k = 0; k < 128; k++) {
            float wv = wc[k * 128];
            ull wd = pack2(wv, wv);
            a01 = fma2(wd, hr[2 * k],     a01);
            a23 = fma2(wd, hr[2 * k + 1], a23);
        }

        if (kh) {
            float2 u = unpk2(a01), v = unpk2(a23);
            sm->red[my_lr][0] = u.x; sm->red[my_lr][1] = u.y;
            sm->red[my_lr][2] = v.x; sm->red[my_lr][3] = v.y;
        }
        __syncthreads();
        if (!kh) {
            float2 u = unpk2(a01), v = unpk2(a23);
            float s0 = u.x + sm->red[my_lr][0] + xv0;
            float s1 = u.y + sm->red[my_lr][1] + xv1;
            float s2 = v.x + sm->red[my_lr][2] + xv2;
            float s3 = v.y + sm->red[my_lr][3] + xv3;
            float a0, a1, a2, a3;
            if (rg == 2) { a0 = ftanh(s0); a1 = ftanh(s1); a2 = ftanh(s2); a3 = ftanh(s3); }
            else         { a0 = fsig(s0);  a1 = fsig(s1);  a2 = fsig(s2);  a3 = fsig(s3);  }
            sm->gates[rg][lane][0] = a0; sm->gates[rg][lane][1] = a1;
            sm->gates[rg][lane][2] = a2; sm->gates[rg][lane][3] = a3;
        }
        __syncthreads();

        if (tid < 128) {  // cell update: thread = b*32 + d
            const int b = tid >> 5, d = tid & 31;
            float iv = sm->gates[0][d][b];
            float fv = sm->gates[1][d][b];
            float gv = sm->gates[2][d][b];
            float ov = sm->gates[3][d][b];
            creg = fv * creg + iv * gv;
            float hv = ov * ftanh(creg);
            yout[((size_t)(b0 + b) * TT + t) * HH + s * 32 + d] = hv;
            // broadcast h to all 8 CTAs' next-step buffer
            uint32_t la = s2u(&sm->h[p ^ 1][s * 32 + d][b]);
            uint32_t hb = __float_as_uint(hv);
#pragma unroll
            for (int rr = 0; rr < 8; rr++) sts_cluster_b32(la, rr, hb);
        }
        cluster_sync_();
    }
}

// ============================================================================
// Head: out[b] = dot(y1[b][T-1][:], w_lin) + b_lin
// ============================================================================
__global__ void head_kernel(const float* __restrict__ wlin,
                            const float* __restrict__ blin,
                            float* __restrict__ out)
{
    int b = blockIdx.x, lane = threadIdx.x;
    const float* hp = g_y1 + ((size_t)b * TT + (TT - 1)) * HH;
    float ssum = 0.0f;
    for (int k = lane; k < HH; k += 32) ssum += hp[k] * wlin[k];
#pragma unroll
    for (int o = 16; o; o >>= 1) ssum += __shfl_down_sync(0xffffffffu, ssum, o);
    if (lane == 0) out[b] = ssum + blin[0];
}

// ============================================================================
extern "C" void kernel_launch(void* const* d_in, const int* in_sizes, int n_in,
                              void* d_out, int out_size)
{
    const float* input = (const float*)d_in[0];
    const float* w_ih  = (const float*)d_in[1];  // [2][1024][256]
    const float* w_hh  = (const float*)d_in[2];  // [2][1024][256]
    const float* b_ih  = (const float*)d_in[3];  // [2][1024]
    const float* b_hh  = (const float*)d_in[4];  // [2][1024]
    const float* w_lin = (const float*)d_in[5];  // [1][256]
    const float* b_lin = (const float*)d_in[6];  // [1]
    float* out = (float*)d_out;

    cudaFuncSetAttribute(rnn_kernel, cudaFuncAttributeMaxDynamicSharedMemorySize,
                         (int)sizeof(RS));

    dim3 gg(G4 / 64, MTOT / 128);

    // Layer 0
    gemm_kernel<<<gg, 256>>>(input, 1, w_ih, b_ih, b_hh);
    rnn_kernel<<<128, 256, sizeof(RS)>>>(w_hh, 0);
    // Layer 1
    gemm_kernel<<<gg, 256>>>(input, 0, w_ih + (size_t)G4 * HH, b_ih + G4, b_hh + G4);
    rnn_kernel<<<128, 256, sizeof(RS)>>>(w_hh + (size_t)G4 * HH, 1);
    // Head
    head_kernel<<<BB, 32>>>(w_lin, b_lin, out);
}

// round 3
// speedup vs baseline: 1.1929x; 1.1929x over previous
#include <cuda_runtime.h>
#include <cstdint>

// Problem constants
#define BB 64
#define TT 2048
#define HH 256
#define G4 1024
#define MTOT (BB * TT)

typedef unsigned long long ull;

// ---------- f32x2 helpers ----------
__device__ __forceinline__ ull fma2(ull a, ull b, ull c) {
    ull d; asm("fma.rn.f32x2 %0,%1,%2,%3;" : "=l"(d) : "l"(a), "l"(b), "l"(c)); return d;
}
__device__ __forceinline__ ull pack2(float x, float y) {
    ull d; asm("mov.b64 %0,{%1,%2};" : "=l"(d) : "f"(x), "f"(y)); return d;
}
__device__ __forceinline__ float2 unpk2(ull a) {
    float2 r; asm("mov.b64 {%0,%1},%2;" : "=f"(r.x), "=f"(r.y) : "l"(a)); return r;
}

__device__ __forceinline__ uint32_t s2u(const void* p) {
    return (uint32_t)__cvta_generic_to_shared(p);
}
__device__ __forceinline__ void sts_cluster_b64(uint32_t saddr, uint32_t rank, ull v) {
    asm volatile(
        "{.reg .b32 ra; mapa.shared::cluster.u32 ra, %0, %1; st.shared::cluster.b64 [ra], %2;}"
        :: "r"(saddr), "r"(rank), "l"(v) : "memory");
}
__device__ __forceinline__ void cluster_sync_() {
    asm volatile("barrier.cluster.arrive.aligned;\n\tbarrier.cluster.wait.aligned;" ::: "memory");
}
__device__ __forceinline__ uint32_t ctarank() {
    uint32_t r; asm("mov.u32 %0, %%cluster_ctarank;" : "=r"(r)); return r;
}

__device__ __forceinline__ float fsig(float x)  { return 1.0f / (1.0f + __expf(-x)); }
__device__ __forceinline__ float ftanh(float x) { return 2.0f / (1.0f + __expf(-2.0f * x)) - 1.0f; }

// ---------- scratch ----------
__device__ float g_xg[(size_t)MTOT * G4];
__device__ float g_y0[(size_t)MTOT * HH];
__device__ float g_y1[(size_t)MTOT * HH];

// ============================================================================
// Phase A: GEMM (unchanged from round 2)
// ============================================================================
__global__ void __launch_bounds__(256) gemm_kernel(
    const float* __restrict__ Ain, int useAin,
    const float* __restrict__ W,
    const float* __restrict__ b1, const float* __restrict__ b2)
{
    const float* A = useAin ? Ain : g_y0;
    float* C = g_xg;

    __shared__ float As[16][132];
    __shared__ float Bs[16][68];

    const int tid = threadIdx.x;
    const int bm = blockIdx.y * 128;
    const int bn = blockIdx.x * 64;
    const int tx = tid & 15;
    const int ty = tid >> 4;

    ull acc[8][2];
#pragma unroll
    for (int i = 0; i < 8; i++) { acc[i][0] = 0ull; acc[i][1] = 0ull; }

    for (int kt = 0; kt < HH; kt += 16) {
#pragma unroll
        for (int i = 0; i < 2; i++) {
            int idx = tid + i * 256;
            int r = idx >> 2, q = idx & 3;
            float4 v = *(const float4*)(A + (size_t)(bm + r) * HH + kt + q * 4);
            As[q * 4 + 0][r] = v.x; As[q * 4 + 1][r] = v.y;
            As[q * 4 + 2][r] = v.z; As[q * 4 + 3][r] = v.w;
        }
        {
            int r = tid >> 2, q = tid & 3;
            float4 v = *(const float4*)(W + (size_t)(bn + r) * HH + kt + q * 4);
            Bs[q * 4 + 0][r] = v.x; Bs[q * 4 + 1][r] = v.y;
            Bs[q * 4 + 2][r] = v.z; Bs[q * 4 + 3][r] = v.w;
        }
        __syncthreads();
#pragma unroll
        for (int k = 0; k < 16; k++) {
            float4 b4 = *(const float4*)&Bs[k][tx * 4];
            ull b01 = pack2(b4.x, b4.y);
            ull b23 = pack2(b4.z, b4.w);
            float4 a0 = *(const float4*)&As[k][ty * 8];
            float4 a1 = *(const float4*)&As[k][ty * 8 + 4];
            float am[8] = {a0.x, a0.y, a0.z, a0.w, a1.x, a1.y, a1.z, a1.w};
#pragma unroll
            for (int mi = 0; mi < 8; mi++) {
                ull ad = pack2(am[mi], am[mi]);
                acc[mi][0] = fma2(ad, b01, acc[mi][0]);
                acc[mi][1] = fma2(ad, b23, acc[mi][1]);
            }
        }
        __syncthreads();
    }

    float4 bias;
    bias.x = b1[bn + tx * 4 + 0] + b2[bn + tx * 4 + 0];
    bias.y = b1[bn + tx * 4 + 1] + b2[bn + tx * 4 + 1];
    bias.z = b1[bn + tx * 4 + 2] + b2[bn + tx * 4 + 2];
    bias.w = b1[bn + tx * 4 + 3] + b2[bn + tx * 4 + 3];
#pragma unroll
    for (int mi = 0; mi < 8; mi++) {
        float2 u = unpk2(acc[mi][0]);
        float2 v = unpk2(acc[mi][1]);
        float4 o = {u.x + bias.x, u.y + bias.y, v.x + bias.z, v.y + bias.w};
        *(float4*)(C + (size_t)(bm + ty * 8 + mi) * G4 + bn + tx * 4) = o;
    }
}

// ============================================================================
// Phase B: recurrent scan v2.
// 16 clusters x 8 CTAs, 512 threads/CTA. w_hh pre-packed in REGISTERS
// (64 regs/thread = 128KB/CTA). h kept duplicated as (v,v) ull in SMEM so the
// inner loop is 2x LDS.128 broadcast + 4x FFMA2 per k (no packing movs).
// 16 warps = 8 k-slices x 2 row-halves; lane owns row pair (2pr, 2pr+1).
// ============================================================================
struct RS {
    ull   hd[2][256][4];     // duplicated h: hd[buf][k][b] = (h,h)   (16KB)
    float red[8][4][128];    // partials: [kslice][batch][row]        (16KB)
    float gates[128][4];     // activated gates [row][batch]          (2KB)
};

extern __shared__ __align__(16) char smem_raw[];

__global__ void __launch_bounds__(512, 1) __cluster_dims__(8, 1, 1)
rnn_kernel(const float* __restrict__ whh, int layer)
{
    RS* sm = (RS*)smem_raw;
    float* yout = layer ? g_y1 : g_y0;

    const int tid  = threadIdx.x;
    const int lane = tid & 31;
    const int wid  = tid >> 5;
    const int rh   = wid & 1;      // row half 0/1
    const int ks   = wid >> 1;     // k slice 0..7
    const int s    = (int)ctarank();
    const int cl   = blockIdx.x >> 3;
    const int b0   = cl * 4;

    const int pr = rh * 32 + lane;        // row-pair index 0..63
    const int r0 = 2 * pr;                // local rows r0, r0+1 (same gate)
    const int g0 = r0 >> 5;
    const int d0 = r0 & 31;
    const int grow0 = g0 * 256 + s * 32 + d0;   // global row of r0 (r1 = +1)
    const int kb = ks * 32;

    // ---- load w slice into registers, pre-packed as (w_r0, w_r1) pairs ----
    ull wp[32];
    {
        const float* w0p = whh + (size_t)grow0 * HH + kb;
        const float* w1p = w0p + HH;
#pragma unroll
        for (int q = 0; q < 8; q++) {
            float4 v0 = *(const float4*)(w0p + 4 * q);
            float4 v1 = *(const float4*)(w1p + 4 * q);
            wp[4 * q + 0] = pack2(v0.x, v1.x);
            wp[4 * q + 1] = pack2(v0.y, v1.y);
            wp[4 * q + 2] = pack2(v0.z, v1.z);
            wp[4 * q + 3] = pack2(v0.w, v1.w);
        }
    }

    // zero both h buffers
    for (int i = tid; i < 2 * 256 * 4; i += 512) ((ull*)sm->hd)[i] = 0ull;
    float creg = 0.0f;  // cell state lives in threads 0..127
    __syncthreads();
    cluster_sync_();

    // reduce-role identity: tid = b*128 + row  (warp-uniform gate)
    const int rb   = tid >> 7;
    const int rrow = tid & 127;
    const int rg   = rrow >> 5;
    const int rd   = rrow & 31;
    const float* xgp = g_xg + (size_t)(b0 + rb) * TT * G4 + (rg * 256 + s * 32 + rd);

    // cell-role identity (tid < 128): tid = b*32 + d
    const int cb = tid >> 5;
    const int cd = tid & 31;
    float* youtp = yout + (size_t)(b0 + cb) * TT * HH + s * 32 + cd;
    const uint32_t la0 = s2u(&sm->hd[0][s * 32 + cd][cb]);
    const uint32_t la1 = s2u(&sm->hd[1][s * 32 + cd][cb]);

    for (int t = 0; t < TT; t++) {
        const int p = t & 1;
        float xv = __ldg(xgp + (size_t)t * G4);   // hidden under k-loop

        // ---- k-loop: acc[b] = (row r0, row r1) sums over this k-slice ----
        ull a0 = 0ull, a1 = 0ull, a2 = 0ull, a3 = 0ull;
        const ulonglong2* hb = (const ulonglong2*)&sm->hd[p][kb][0];
#pragma unroll
        for (int kk = 0; kk < 32; kk++) {
            ulonglong2 h01 = hb[2 * kk];       // (b0b0, b1b1)
            ulonglong2 h23 = hb[2 * kk + 1];   // (b2b2, b3b3)
            ull w = wp[kk];
            a0 = fma2(w, h01.x, a0);
            a1 = fma2(w, h01.y, a1);
            a2 = fma2(w, h23.x, a2);
            a3 = fma2(w, h23.y, a3);
        }
        // store partials: (r0,r1) adjacent floats -> conflict-free STS.64
        *(ull*)&sm->red[ks][0][r0] = a0;
        *(ull*)&sm->red[ks][1][r0] = a1;
        *(ull*)&sm->red[ks][2][r0] = a2;
        *(ull*)&sm->red[ks][3][r0] = a3;
        __syncthreads();

        // ---- reduce + activation (all 512 threads, conflict-free reads) ----
        {
            float ssum = xv;
#pragma unroll
            for (int s8 = 0; s8 < 8; s8++) ssum += sm->red[s8][rb][rrow];
            float av = (rg == 2) ? ftanh(ssum) : fsig(ssum);
            sm->gates[rrow][rb] = av;
        }
        __syncthreads();

        // ---- cell update + duplicated-h broadcast to all 8 CTAs ----
        if (tid < 128) {
            float iv = sm->gates[cd][cb];
            float fv = sm->gates[32 + cd][cb];
            float gv = sm->gates[64 + cd][cb];
            float ov = sm->gates[96 + cd][cb];
            creg = fv * creg + iv * gv;
            float hv = ov * ftanh(creg);
            youtp[(size_t)t * HH] = hv;
            ull hvd = pack2(hv, hv);
            uint32_t la = p ? la0 : la1;   // write buffer p^1
#pragma unroll
            for (int rr = 0; rr < 8; rr++) sts_cluster_b64(la, rr, hvd);
        }
        cluster_sync_();
    }
}

// ============================================================================
// Head
// ============================================================================
__global__ void head_kernel(const float* __restrict__ wlin,
                            const float* __restrict__ blin,
                            float* __restrict__ out)
{
    int b = blockIdx.x, lane = threadIdx.x;
    const float* hp = g_y1 + ((size_t)b * TT + (TT - 1)) * HH;
    float ssum = 0.0f;
    for (int k = lane; k < HH; k += 32) ssum += hp[k] * wlin[k];
#pragma unroll
    for (int o = 16; o; o >>= 1) ssum += __shfl_down_sync(0xffffffffu, ssum, o);
    if (lane == 0) out[b] = ssum + blin[0];
}

// ============================================================================
extern "C" void kernel_launch(void* const* d_in, const int* in_sizes, int n_in,
                              void* d_out, int out_size)
{
    const float* input = (const float*)d_in[0];
    const float* w_ih  = (const float*)d_in[1];
    const float* w_hh  = (const float*)d_in[2];
    const float* b_ih  = (const float*)d_in[3];
    const float* b_hh  = (const float*)d_in[4];
    const float* w_lin = (const float*)d_in[5];
    const float* b_lin = (const float*)d_in[6];
    float* out = (float*)d_out;

    cudaFuncSetAttribute(rnn_kernel, cudaFuncAttributeMaxDynamicSharedMemorySize,
                         (int)sizeof(RS));

    dim3 gg(G4 / 64, MTOT / 128);

    gemm_kernel<<<gg, 256>>>(input, 1, w_ih, b_ih, b_hh);
    rnn_kernel<<<128, 512, sizeof(RS)>>>(w_hh, 0);
    gemm_kernel<<<gg, 256>>>(input, 0, w_ih + (size_t)G4 * HH, b_ih + G4, b_hh + G4);
    rnn_kernel<<<128, 512, sizeof(RS)>>>(w_hh + (size_t)G4 * HH, 1);
    head_kernel<<<BB, 32>>>(w_lin, b_lin, out);
}